// round 16
// baseline (speedup 1.0000x reference)
#include <cuda_runtime.h>
#include <cuda_bf16.h>
#include <cstdint>
#include <math.h>

#define HH 1024
#define NIMG 6
#define HW (HH*HH)
#define EPSF 1e-3f

typedef unsigned short u16;
typedef unsigned int u32;

// ---------------- device scratch (allocation-free rule) ---------------------
__device__ u16 g_Ah[3*HW];          // blur matrices, bf16 hi, [sigma][i][j]
__device__ u16 g_Al[3*HW];          // lo
__device__ u16 g_XTh[NIMG*HW];      // clipped input transposed [img][x][u], hi
__device__ u16 g_XTl[NIMG*HW];      // lo
__device__ u16 g_Yh[3*NIMG*HW];     // vertical blur [sigma][img][y][x], hi
__device__ u16 g_Yl[3*NIMG*HW];     // lo
__device__ float g_accS[3*NIMG*HW]; // log(blur_sigma) [sigma][img][y][x]
__device__ float g_kern[2304];      // 1D kernels at offsets 0,128,640
__device__ float g_red[4];

__constant__ int c_p[3] = {45, 240, 750};

__device__ __forceinline__ u32 smem_u32(const void* p) {
    u32 a;
    asm("{ .reg .u64 t; cvta.to.shared.u64 t, %1; cvt.u32.u64 %0, t; }" : "=r"(a) : "l"(p));
    return a;
}
#define LDSM4(r, addr) asm volatile( \
    "ldmatrix.sync.aligned.m8n8.x4.shared.b16 {%0,%1,%2,%3}, [%4];" \
    : "=r"((r)[0]),"=r"((r)[1]),"=r"((r)[2]),"=r"((r)[3]) : "r"(addr))
#define MMA16816(dd, aa, b0, b1) asm volatile( \
    "mma.sync.aligned.m16n8k16.row.col.f32.bf16.bf16.f32 " \
    "{%0,%1,%2,%3},{%4,%5,%6,%7},{%8,%9},{%0,%1,%2,%3};" \
    : "+f"((dd)[0]),"+f"((dd)[1]),"+f"((dd)[2]),"+f"((dd)[3]) \
    : "r"((aa)[0]),"r"((aa)[1]),"r"((aa)[2]),"r"((aa)[3]), "r"(b0), "r"(b1))
#define CP16(dst, src)  asm volatile("cp.async.cg.shared.global [%0], [%1], 16;" :: "r"(dst), "l"(src))
#define CP_COMMIT()     asm volatile("cp.async.commit_group;" ::: "memory")
#define CP_WAIT0()      asm volatile("cp.async.wait_group 0;" ::: "memory")
#define CP_WAIT1()      asm volatile("cp.async.wait_group 1;" ::: "memory")

__device__ __forceinline__ void bf_split(float v, u16& h, u16& l) {
    __nv_bfloat16 bh = __float2bfloat16(v);
    h = __bfloat16_as_ushort(bh);
    l = __bfloat16_as_ushort(__float2bfloat16(v - __bfloat162float(bh)));
}

// ---------------------------------------------------------------------------
__global__ void init_kernels_k() {
    __shared__ float red[1024];
    const float sig[3] = {15.f, 80.f, 250.f};
    const int   ks [3] = {91, 481, 1501};
    const int   off[3] = {0, 128, 640};
    int tid = threadIdx.x;
    if (tid < 4) g_red[tid] = 0.f;
    for (int s = 0; s < 3; ++s) {
        int n = ks[s];
        float c = 0.5f * (float)(n - 1), inv = 1.0f / sig[s], local = 0.f;
        for (int t = tid; t < n; t += 1024) {
            float x = ((float)t - c) * inv;
            float v = expf(-0.5f * x * x);
            g_kern[off[s] + t] = v;
            local += v;
        }
        red[tid] = local;
        __syncthreads();
        for (int st = 512; st > 0; st >>= 1) {
            if (tid < st) red[tid] += red[tid + st];
            __syncthreads();
        }
        float s_inv = 1.0f / red[0];
        __syncthreads();
        for (int t = tid; t < n; t += 1024) g_kern[off[s] + t] *= s_inv;
    }
}

// ---------------------------------------------------------------------------
// Exact reflect-pad blur matrix, split bf16 hi/lo.
// A[i][j] = kt(j-i+p) + [j>0] kt(-j-i+p) + [j<1023] kt(2046-j-i+p)
// ---------------------------------------------------------------------------
__global__ void buildA_k() {
    const int ks [3] = {91, 481, 1501};
    const int off[3] = {0, 128, 640};
    const int pp [3] = {45, 240, 750};
    int i = blockIdx.x, s = blockIdx.y;
    int koff = off[s], kn = ks[s], p = pp[s];
    size_t base = (size_t)s * HW + (size_t)i * 1024;
    for (int j = threadIdx.x; j < 1024; j += blockDim.x) {
        float v = 0.f;
        int t0 = j - i + p;
        if (t0 >= 0 && t0 < kn) v += g_kern[koff + t0];
        int t1 = -j - i + p;
        if (j > 0 && t1 >= 0 && t1 < kn) v += g_kern[koff + t1];
        int t2 = 2046 - j - i + p;
        if (j < 1023 && t2 >= 0 && t2 < kn) v += g_kern[koff + t2];
        u16 h, l;
        bf_split(v, h, l);
        g_Ah[base + j] = h;
        g_Al[base + j] = l;
    }
}

__global__ void splitX_k(const float* __restrict__ inp) {
    __shared__ float sm[32][33];
    int x0 = blockIdx.x * 32, y0 = blockIdx.y * 32, img = blockIdx.z;
    int tx = threadIdx.x, ty = threadIdx.y;
    float v = inp[(size_t)img * HW + (size_t)(y0 + ty) * 1024 + x0 + tx];
    sm[ty][tx] = fminf(fmaxf(v, EPSF), 1.0f);
    __syncthreads();
    float w = sm[tx][ty];
    u16 h, l;
    bf_split(w, h, l);
    size_t o = (size_t)img * HW + (size_t)(x0 + ty) * 1024 + y0 + tx;
    g_XTh[o] = h;
    g_XTl[o] = l;
}

// ---------------------------------------------------------------------------
// Banded bf16x3 GEMM on mma.sync (base-ISA HMMA), 3-buffer cp.async pipeline
// staged 2 slabs ahead, ONE barrier per K-slab (R12 scheme, proven correct).
// NEW vs R12: 256-thread CTA, 8 warps, warp tile m64 x n64 — halves per-MAC
// LDSM traffic (128KB/slab/SM = 1024cyc < 1536cyc tensor floor), so the
// smem crossbar no longer co-limits the tensor pipe.
//   PASS1: tile 128x256, warps 2x4. P=A_s rows y (band driver), Q=XT.
//   PASS2: tile 256x128, warps 4x2. P=Y_s, Q=A_s rows x (band driver = N ext).
// smem rows padded to 80B (ldmatrix conflict-free); 3 x 60KB buffers.
// a-frag registers are REUSED for lo-A (hi-A dead after product g2): ~200 regs.
// ---------------------------------------------------------------------------
#define BUF 61440
#define SMEM_MMA (3*BUF)
#define MTHR 256

template<int TM, int TN>
__device__ __forceinline__ void stage_slab(u32 sa, const u16* Ph, const u16* Pl,
                                           const u16* Qh, const u16* Ql,
                                           int m0, int n0, int k0, int tid) {
    const int OPL = TM * 80, OQH = 2 * TM * 80, OQL = 2 * TM * 80 + TN * 80;
#pragma unroll
    for (int q = 0; q < TM / 64; ++q) {
        int it = tid + q * MTHR, prow = it >> 2, pg = it & 3;
        size_t src = ((size_t)(m0 + prow) * 1024 + k0) * 2 + pg * 16;
        CP16(sa + prow * 80 + pg * 16, (const char*)Ph + src);
        CP16(sa + OPL + prow * 80 + pg * 16, (const char*)Pl + src);
    }
#pragma unroll
    for (int q = 0; q < TN / 64; ++q) {
        int it = tid + q * MTHR, qrow = it >> 2, qg = it & 3;
        size_t src = ((size_t)(n0 + qrow) * 1024 + k0) * 2 + qg * 16;
        CP16(sa + OQH + qrow * 80 + qg * 16, (const char*)Qh + src);
        CP16(sa + OQL + qrow * 80 + qg * 16, (const char*)Ql + src);
    }
}

template<int PASS>
__global__ void __launch_bounds__(MTHR) mma_k() {
    constexpr int TM = (PASS == 1) ? 128 : 256;
    constexpr int TN = (PASS == 1) ? 256 : 128;
    constexpr int WN = TN / 64;                 // n-warps (4 or 2), warp n64
    const int OPL = TM * 80, OQH = 2 * TM * 80, OQL = 2 * TM * 80 + TN * 80;

    extern __shared__ char sm[];
    u32 sb = smem_u32(sm);
    int tid = threadIdx.x, wid = tid >> 5, l = tid & 31;
    int wm = wid / WN, wn = wid % WN;

    int sigma = blockIdx.x % 3;
    int blk   = blockIdx.x / 3;
    int p = c_p[sigma];
    int m0 = blk * TM, n0 = blockIdx.y * TN;
    const u16 *Ph, *Pl, *Qh, *Ql;
    if (PASS == 1) {
        Ph = g_Ah + (size_t)sigma * HW;  Pl = g_Al + (size_t)sigma * HW;
        Qh = g_XTh;                      Ql = g_XTl;
    } else {
        Ph = g_Yh + (size_t)sigma * (NIMG * HW);
        Pl = g_Yl + (size_t)sigma * (NIMG * HW);
        Qh = g_Ah + (size_t)sigma * HW;  Ql = g_Al + (size_t)sigma * HW;
    }
    int c0   = (PASS == 1) ? m0 : n0;
    int kmin = max(0, c0 - p) & ~31;
    int kmax = min(1024, (c0 + ((PASS == 1) ? TM : TN) + p + 31) & ~31);
    int nslab = (kmax - kmin) >> 5;

    float d[32][4];
#pragma unroll
    for (int i = 0; i < 32; ++i)
#pragma unroll
        for (int j = 0; j < 4; ++j) d[i][j] = 0.f;

    u32 aoff = (u32)(((l & 7) + ((l >> 3) & 1) * 8) * 80 + (l >> 4) * 16);
    u32 boff = (u32)(((l & 7) + ((l >> 4) & 1) * 8) * 80 + ((l >> 3) & 1) * 16);

    // warmup: prefetch 2 slabs (slots 0, 1)
    int prefetched = 0;
#pragma unroll
    for (int w = 0; w < 2; ++w) {
        if (w < nslab) {
            stage_slab<TM, TN>(sb + w * BUF, Ph, Pl, Qh, Ql, m0, n0, kmin + w * 32, tid);
            CP_COMMIT();
            ++prefetched;
        }
    }

    for (int i = 0; i < nslab; ++i) {
        if (prefetched - i - 1 > 0) CP_WAIT1(); else CP_WAIT0();
        __syncthreads();                      // single barrier per slab
        u32 sbuf = sb + (u32)(i % 3) * BUF;
        u32 aPh = sbuf + wm * (64 * 80) + aoff;
        u32 aPl = sbuf + OPL + wm * (64 * 80) + aoff;
        u32 bQh = sbuf + OQH + wn * (64 * 80) + boff;
        u32 bQl = sbuf + OQL + wn * (64 * 80) + boff;
#pragma unroll
        for (int kb = 0; kb < 2; ++kb) {
            u32 a[4][4], b1[4][4], b2[4][4];
#pragma unroll
            for (int mi = 0; mi < 4; ++mi) LDSM4(a[mi], aPh + mi * (16 * 80) + kb * 32);
#pragma unroll
            for (int nj = 0; nj < 4; ++nj) LDSM4(b1[nj], bQh + nj * (16 * 80) + kb * 32);
#pragma unroll
            for (int nj = 0; nj < 4; ++nj) LDSM4(b2[nj], bQl + nj * (16 * 80) + kb * 32);
            // g1: Phi x Qhi
#pragma unroll
            for (int mi = 0; mi < 4; ++mi)
#pragma unroll
                for (int ni = 0; ni < 8; ++ni)
                    MMA16816(d[mi * 8 + ni], a[mi], b1[ni >> 1][(ni & 1) * 2], b1[ni >> 1][(ni & 1) * 2 + 1]);
            // g2: Phi x Qlo
#pragma unroll
            for (int mi = 0; mi < 4; ++mi)
#pragma unroll
                for (int ni = 0; ni < 8; ++ni)
                    MMA16816(d[mi * 8 + ni], a[mi], b2[ni >> 1][(ni & 1) * 2], b2[ni >> 1][(ni & 1) * 2 + 1]);
            // hi-A is dead now: reuse its registers for lo-A
#pragma unroll
            for (int mi = 0; mi < 4; ++mi) LDSM4(a[mi], aPl + mi * (16 * 80) + kb * 32);
            // g3: Plo x Qhi
#pragma unroll
            for (int mi = 0; mi < 4; ++mi)
#pragma unroll
                for (int ni = 0; ni < 8; ++ni)
                    MMA16816(d[mi * 8 + ni], a[mi], b1[ni >> 1][(ni & 1) * 2], b1[ni >> 1][(ni & 1) * 2 + 1]);
        }
        // stage slab i+2 into slot (i+2)%3 — last read at iter i-1, safe.
        if (prefetched < nslab) {
            stage_slab<TM, TN>(sb + (u32)(prefetched % 3) * BUF, Ph, Pl, Qh, Ql,
                               m0, n0, kmin + prefetched * 32, tid);
            CP_COMMIT();
            ++prefetched;
        }
    }

    // epilogue: d-frag map: rows t/4 (+8), cols (t%4)*2 (+1)
#pragma unroll
    for (int mi = 0; mi < 4; ++mi) {
#pragma unroll
        for (int ni = 0; ni < 8; ++ni) {
            float* dd = d[mi * 8 + ni];
            int gm0 = m0 + wm * 64 + mi * 16 + (l >> 2);
            int gc  = n0 + wn * 64 + ni * 8 + (l & 3) * 2;
#pragma unroll
            for (int h = 0; h < 2; ++h) {
                int gm = gm0 + h * 8;
                float v0 = dd[h * 2 + 0], v1 = dd[h * 2 + 1];
                if (PASS == 1) {
                    // out: Y[sigma][img = gc>>10][y = gm][x = gc&1023]
                    size_t o = (size_t)sigma * (NIMG * HW)
                             + ((size_t)(gc >> 10)) * HW + (size_t)gm * 1024 + (gc & 1023);
                    u16 h0, l0, h1, l1;
                    bf_split(v0, h0, l0);
                    bf_split(v1, h1, l1);
                    *(u32*)&g_Yh[o] = (u32)h0 | ((u32)h1 << 16);
                    *(u32*)&g_Yl[o] = (u32)l0 | ((u32)l1 << 16);
                } else {
                    // out: accS[sigma][gm = img*1024+y][gc = x]
                    size_t o = (size_t)sigma * (NIMG * HW) + (size_t)gm * 1024 + gc;
                    g_accS[o]     = logf(fmaxf(v0, EPSF));
                    g_accS[o + 1] = logf(fmaxf(v1, EPSF));
                }
            }
        }
    }
}

// ---------------------------------------------------------------------------
__global__ void fields_k(const float* __restrict__ inp, float* __restrict__ dout) {
    int total = NIMG * HW;
    for (int idx = blockIdx.x * blockDim.x + threadIdx.x; idx < total;
         idx += gridDim.x * blockDim.x) {
        float a = g_accS[idx] + g_accS[total + idx] + g_accS[2 * total + idx];
        float ib = a * (1.0f / 3.0f);
        float v  = inp[idx];
        float li = logf(fminf(fmaxf(v, EPSF), 1.0f));
        float refl  = li - ib;
        float illum = logf(fmaxf(v, EPSF)) - refl;
        dout[3 + idx]         = refl;
        dout[3 + total + idx] = illum;
    }
}

__global__ void grad_k(const float* __restrict__ dout) {
    const float* __restrict__ refl = dout + 3;
    const float* __restrict__ ill  = dout + 3 + NIMG * HW;
    float s0 = 0.f, s1 = 0.f, s2 = 0.f, s3 = 0.f;
    int total = NIMG * HW;
    for (int idx = blockIdx.x * blockDim.x + threadIdx.x; idx < total;
         idx += gridDim.x * blockDim.x) {
        int x = idx & 1023, y = (idx >> 10) & 1023;
        float r0 = refl[idx], i0 = ill[idx];
        if (x < 1023) { s0 += fabsf(r0 - refl[idx + 1]);    s2 += fabsf(i0 - ill[idx + 1]); }
        if (y < 1023) { s1 += fabsf(r0 - refl[idx + 1024]); s3 += fabsf(i0 - ill[idx + 1024]); }
    }
#pragma unroll
    for (int o = 16; o > 0; o >>= 1) {
        s0 += __shfl_down_sync(0xffffffffu, s0, o);
        s1 += __shfl_down_sync(0xffffffffu, s1, o);
        s2 += __shfl_down_sync(0xffffffffu, s2, o);
        s3 += __shfl_down_sync(0xffffffffu, s3, o);
    }
    __shared__ float sb[4][8];
    int wid = threadIdx.x >> 5, lid = threadIdx.x & 31;
    if (lid == 0) { sb[0][wid] = s0; sb[1][wid] = s1; sb[2][wid] = s2; sb[3][wid] = s3; }
    __syncthreads();
    if (threadIdx.x == 0) {
        float t0 = 0.f, t1 = 0.f, t2 = 0.f, t3 = 0.f;
        int nw = blockDim.x >> 5;
        for (int w = 0; w < nw; ++w) { t0 += sb[0][w]; t1 += sb[1][w]; t2 += sb[2][w]; t3 += sb[3][w]; }
        atomicAdd(&g_red[0], t0); atomicAdd(&g_red[1], t1);
        atomicAdd(&g_red[2], t2); atomicAdd(&g_red[3], t3);
    }
}

__global__ void fin_k(float* dout) {
    if (threadIdx.x == 0) {
        float ngx = (float)(NIMG * 1024 * 1023);
        float ngy = (float)(NIMG * 1023 * 1024);
        float ld = g_red[0] / ngx + g_red[1] / ngy;
        float ls = g_red[2] / ngx + g_red[3] / ngy;
        dout[0] = ls; dout[1] = ld; dout[2] = ls;   // DETAIL_W=0, ILLUM_W=1
    }
}

extern "C" void kernel_launch(void* const* d_in, const int* in_sizes, int n_in,
                              void* d_out, int out_size) {
    const float* inp = (const float*)d_in[0];
    float* out = (float*)d_out;

    cudaFuncSetAttribute(mma_k<1>, cudaFuncAttributeMaxDynamicSharedMemorySize, SMEM_MMA);
    cudaFuncSetAttribute(mma_k<2>, cudaFuncAttributeMaxDynamicSharedMemorySize, SMEM_MMA);

    init_kernels_k<<<1, 1024>>>();
    buildA_k<<<dim3(1024, 3), 256>>>();
    splitX_k<<<dim3(32, 32, NIMG), dim3(32, 32)>>>(inp);

    // sigma = blockIdx.x % 3 (interleaved load balance), all sigmas per launch
    mma_k<1><<<dim3(8 * 3, 24), MTHR, SMEM_MMA>>>();   // Y[s] = A_s * X   (tile 128x256)
    mma_k<2><<<dim3(24 * 3, 8), MTHR, SMEM_MMA>>>();   // accS[s] = log(Y_s * A_s^T) (256x128)

    fields_k<<<4096, 256>>>(inp, out);
    grad_k<<<2048, 256>>>(out);
    fin_k<<<1, 32>>>(out);
}

// round 17
// speedup vs baseline: 1.0717x; 1.0717x over previous
#include <cuda_runtime.h>
#include <cuda_bf16.h>
#include <cstdint>
#include <math.h>

#define HH 1024
#define NIMG 6
#define HW (HH*HH)
#define EPSF 1e-3f

typedef unsigned short u16;
typedef unsigned int u32;

// ---------------- device scratch (allocation-free rule) ---------------------
__device__ u16 g_Ah[3*HW];          // blur matrices, bf16 hi, [sigma][i][j]
__device__ u16 g_Al[3*HW];          // lo
__device__ u16 g_XTh[NIMG*HW];      // clipped input transposed [img][x][u], hi
__device__ u16 g_XTl[NIMG*HW];      // lo
__device__ u16 g_Yh[3*NIMG*HW];     // vertical blur [sigma][img][y][x], hi
__device__ u16 g_Yl[3*NIMG*HW];     // lo
__device__ float g_accS[3*NIMG*HW]; // log(blur_sigma) [sigma][img][y][x]
__device__ float g_kern[2304];      // 1D kernels at offsets 0,128,640
__device__ float g_red[4];

__constant__ int c_p[3] = {45, 240, 750};

__device__ __forceinline__ u32 smem_u32(const void* p) {
    u32 a;
    asm("{ .reg .u64 t; cvta.to.shared.u64 t, %1; cvt.u32.u64 %0, t; }" : "=r"(a) : "l"(p));
    return a;
}
#define LDSM4(r, addr) asm volatile( \
    "ldmatrix.sync.aligned.m8n8.x4.shared.b16 {%0,%1,%2,%3}, [%4];" \
    : "=r"((r)[0]),"=r"((r)[1]),"=r"((r)[2]),"=r"((r)[3]) : "r"(addr))
#define MMA16816(dd, aa, b0, b1) asm volatile( \
    "mma.sync.aligned.m16n8k16.row.col.f32.bf16.bf16.f32 " \
    "{%0,%1,%2,%3},{%4,%5,%6,%7},{%8,%9},{%0,%1,%2,%3};" \
    : "+f"((dd)[0]),"+f"((dd)[1]),"+f"((dd)[2]),"+f"((dd)[3]) \
    : "r"((aa)[0]),"r"((aa)[1]),"r"((aa)[2]),"r"((aa)[3]), "r"(b0), "r"(b1))
#define CP16(dst, src)  asm volatile("cp.async.cg.shared.global [%0], [%1], 16;" :: "r"(dst), "l"(src))
#define CP_COMMIT()     asm volatile("cp.async.commit_group;" ::: "memory")
#define CP_WAIT0()      asm volatile("cp.async.wait_group 0;" ::: "memory")

__device__ __forceinline__ void bf_split(float v, u16& h, u16& l) {
    __nv_bfloat16 bh = __float2bfloat16(v);
    h = __bfloat16_as_ushort(bh);
    l = __bfloat16_as_ushort(__float2bfloat16(v - __bfloat162float(bh)));
}

// ---------------------------------------------------------------------------
__global__ void init_kernels_k() {
    __shared__ float red[1024];
    const float sig[3] = {15.f, 80.f, 250.f};
    const int   ks [3] = {91, 481, 1501};
    const int   off[3] = {0, 128, 640};
    int tid = threadIdx.x;
    if (tid < 4) g_red[tid] = 0.f;
    for (int s = 0; s < 3; ++s) {
        int n = ks[s];
        float c = 0.5f * (float)(n - 1), inv = 1.0f / sig[s], local = 0.f;
        for (int t = tid; t < n; t += 1024) {
            float x = ((float)t - c) * inv;
            float v = expf(-0.5f * x * x);
            g_kern[off[s] + t] = v;
            local += v;
        }
        red[tid] = local;
        __syncthreads();
        for (int st = 512; st > 0; st >>= 1) {
            if (tid < st) red[tid] += red[tid + st];
            __syncthreads();
        }
        float s_inv = 1.0f / red[0];
        __syncthreads();
        for (int t = tid; t < n; t += 1024) g_kern[off[s] + t] *= s_inv;
    }
}

// ---------------------------------------------------------------------------
// Exact reflect-pad blur matrix, split bf16 hi/lo.
// A[i][j] = kt(j-i+p) + [j>0] kt(-j-i+p) + [j<1023] kt(2046-j-i+p)
// ---------------------------------------------------------------------------
__global__ void buildA_k() {
    const int ks [3] = {91, 481, 1501};
    const int off[3] = {0, 128, 640};
    const int pp [3] = {45, 240, 750};
    int i = blockIdx.x, s = blockIdx.y;
    int koff = off[s], kn = ks[s], p = pp[s];
    size_t base = (size_t)s * HW + (size_t)i * 1024;
    for (int j = threadIdx.x; j < 1024; j += blockDim.x) {
        float v = 0.f;
        int t0 = j - i + p;
        if (t0 >= 0 && t0 < kn) v += g_kern[koff + t0];
        int t1 = -j - i + p;
        if (j > 0 && t1 >= 0 && t1 < kn) v += g_kern[koff + t1];
        int t2 = 2046 - j - i + p;
        if (j < 1023 && t2 >= 0 && t2 < kn) v += g_kern[koff + t2];
        u16 h, l;
        bf_split(v, h, l);
        g_Ah[base + j] = h;
        g_Al[base + j] = l;
    }
}

__global__ void splitX_k(const float* __restrict__ inp) {
    __shared__ float sm[32][33];
    int x0 = blockIdx.x * 32, y0 = blockIdx.y * 32, img = blockIdx.z;
    int tx = threadIdx.x, ty = threadIdx.y;
    float v = inp[(size_t)img * HW + (size_t)(y0 + ty) * 1024 + x0 + tx];
    sm[ty][tx] = fminf(fmaxf(v, EPSF), 1.0f);
    __syncthreads();
    float w = sm[tx][ty];
    u16 h, l;
    bf_split(w, h, l);
    size_t o = (size_t)img * HW + (size_t)(x0 + ty) * 1024 + y0 + tx;
    g_XTh[o] = h;
    g_XTl[o] = l;
}

// ---------------------------------------------------------------------------
// Banded bf16x3 GEMM on mma.sync (base-ISA HMMA).
// R16 config: tile 128x128, 256 thr = 8 warps (2 m x 4 n), warp tile m64 x n32
// (the proven R12 warp shape, ~128 regs). 2-stage cp.async pipeline
// (2 x 40KB buffers = 80KB smem) -> TWO CTAs co-resident per SM: two
// independent barrier domains, so one CTA's MMAs cover the other's
// CP_WAIT/__syncthreads/LDSM-ramp bubbles (R12's limiter at tensor=51.7%).
// Total MACs identical to R12: pass1 band driven by TM=128, pass2 by TN=128.
//   At iter i: read slot i%2; stage slab i+1 into slot (i+1)%2 (last read at
//   iter i-1, ordered by the top-of-iter-i barrier). CP_WAIT0 before barrier.
// smem rows padded to 80B (ldmatrix conflict-free).
// ---------------------------------------------------------------------------
#define BUF 40960
#define SMEM_MMA (2*BUF)
#define MTHR 256

template<int TM, int TN>
__device__ __forceinline__ void stage_slab(u32 sa, const u16* Ph, const u16* Pl,
                                           const u16* Qh, const u16* Ql,
                                           int m0, int n0, int k0, int tid) {
    const int OPL = TM * 80, OQH = 2 * TM * 80, OQL = 2 * TM * 80 + TN * 80;
#pragma unroll
    for (int q = 0; q < TM * 4 / MTHR; ++q) {
        int it = tid + q * MTHR, prow = it >> 2, pg = it & 3;
        size_t src = ((size_t)(m0 + prow) * 1024 + k0) * 2 + pg * 16;
        CP16(sa + prow * 80 + pg * 16, (const char*)Ph + src);
        CP16(sa + OPL + prow * 80 + pg * 16, (const char*)Pl + src);
    }
#pragma unroll
    for (int q = 0; q < TN * 4 / MTHR; ++q) {
        int it = tid + q * MTHR, qrow = it >> 2, qg = it & 3;
        size_t src = ((size_t)(n0 + qrow) * 1024 + k0) * 2 + qg * 16;
        CP16(sa + OQH + qrow * 80 + qg * 16, (const char*)Qh + src);
        CP16(sa + OQL + qrow * 80 + qg * 16, (const char*)Ql + src);
    }
}

template<int PASS>
__global__ void __launch_bounds__(MTHR, 2) mma_k() {
    constexpr int TM = 128;
    constexpr int TN = 128;
    constexpr int WN = 4;                        // 8 warps: 2 m x 4 n, warp m64 x n32
    const int OPL = TM * 80, OQH = 2 * TM * 80, OQL = 2 * TM * 80 + TN * 80;

    extern __shared__ char sm[];
    u32 sb = smem_u32(sm);
    int tid = threadIdx.x, wid = tid >> 5, l = tid & 31;
    int wm = wid / WN, wn = wid % WN;

    int sigma = blockIdx.x % 3;
    int blk   = blockIdx.x / 3;
    int p = c_p[sigma];
    int m0 = blk * TM, n0 = blockIdx.y * TN;
    const u16 *Ph, *Pl, *Qh, *Ql;
    if (PASS == 1) {
        Ph = g_Ah + (size_t)sigma * HW;  Pl = g_Al + (size_t)sigma * HW;
        Qh = g_XTh;                      Ql = g_XTl;
    } else {
        Ph = g_Yh + (size_t)sigma * (NIMG * HW);
        Pl = g_Yl + (size_t)sigma * (NIMG * HW);
        Qh = g_Ah + (size_t)sigma * HW;  Ql = g_Al + (size_t)sigma * HW;
    }
    int c0   = (PASS == 1) ? m0 : n0;
    int kmin = max(0, c0 - p) & ~31;
    int kmax = min(1024, (c0 + 128 + p + 31) & ~31);
    int nslab = (kmax - kmin) >> 5;

    float d[16][4];
#pragma unroll
    for (int i = 0; i < 16; ++i)
#pragma unroll
        for (int j = 0; j < 4; ++j) d[i][j] = 0.f;

    u32 aoff = (u32)(((l & 7) + ((l >> 3) & 1) * 8) * 80 + (l >> 4) * 16);
    u32 boff = (u32)(((l & 7) + ((l >> 4) & 1) * 8) * 80 + ((l >> 3) & 1) * 16);

    // warmup: prefetch slab 0 into slot 0
    stage_slab<TM, TN>(sb, Ph, Pl, Qh, Ql, m0, n0, kmin, tid);
    CP_COMMIT();
    int prefetched = 1;

    for (int i = 0; i < nslab; ++i) {
        CP_WAIT0();
        __syncthreads();                      // single barrier per slab
        u32 sbuf = sb + (u32)(i & 1) * BUF;
        u32 aPh = sbuf + wm * (64 * 80) + aoff;
        u32 aPl = sbuf + OPL + wm * (64 * 80) + aoff;
        u32 bQh = sbuf + OQH + wn * (32 * 80) + boff;
        u32 bQl = sbuf + OQL + wn * (32 * 80) + boff;
#pragma unroll
        for (int kb = 0; kb < 2; ++kb) {
            u32 a[4][4], a2[4][4], b1[2][4], b2[2][4];
#pragma unroll
            for (int mi = 0; mi < 4; ++mi) LDSM4(a[mi], aPh + mi * (16 * 80) + kb * 32);
#pragma unroll
            for (int nj = 0; nj < 2; ++nj) LDSM4(b1[nj], bQh + nj * (16 * 80) + kb * 32);
#pragma unroll
            for (int nj = 0; nj < 2; ++nj) LDSM4(b2[nj], bQl + nj * (16 * 80) + kb * 32);
            // g1: Phi x Qhi
#pragma unroll
            for (int mi = 0; mi < 4; ++mi)
#pragma unroll
                for (int ni = 0; ni < 4; ++ni)
                    MMA16816(d[mi * 4 + ni], a[mi], b1[ni >> 1][(ni & 1) * 2], b1[ni >> 1][(ni & 1) * 2 + 1]);
#pragma unroll
            for (int mi = 0; mi < 4; ++mi) LDSM4(a2[mi], aPl + mi * (16 * 80) + kb * 32);
            // g2: Phi x Qlo
#pragma unroll
            for (int mi = 0; mi < 4; ++mi)
#pragma unroll
                for (int ni = 0; ni < 4; ++ni)
                    MMA16816(d[mi * 4 + ni], a[mi], b2[ni >> 1][(ni & 1) * 2], b2[ni >> 1][(ni & 1) * 2 + 1]);
            // g3: Plo x Qhi
#pragma unroll
            for (int mi = 0; mi < 4; ++mi)
#pragma unroll
                for (int ni = 0; ni < 4; ++ni)
                    MMA16816(d[mi * 4 + ni], a2[mi], b1[ni >> 1][(ni & 1) * 2], b1[ni >> 1][(ni & 1) * 2 + 1]);
        }
        // stage slab i+1 into slot (i+1)%2 — last read at iter i-1, safe.
        if (prefetched < nslab) {
            stage_slab<TM, TN>(sb + (u32)(prefetched & 1) * BUF, Ph, Pl, Qh, Ql,
                               m0, n0, kmin + prefetched * 32, tid);
            CP_COMMIT();
            ++prefetched;
        }
    }

    // epilogue: d-frag map: rows t/4 (+8), cols (t%4)*2 (+1)
#pragma unroll
    for (int mi = 0; mi < 4; ++mi) {
#pragma unroll
        for (int ni = 0; ni < 4; ++ni) {
            float* dd = d[mi * 4 + ni];
            int gm0 = m0 + wm * 64 + mi * 16 + (l >> 2);
            int gc  = n0 + wn * 32 + ni * 8 + (l & 3) * 2;
#pragma unroll
            for (int h = 0; h < 2; ++h) {
                int gm = gm0 + h * 8;
                float v0 = dd[h * 2 + 0], v1 = dd[h * 2 + 1];
                if (PASS == 1) {
                    // out: Y[sigma][img = gc>>10][y = gm][x = gc&1023]
                    size_t o = (size_t)sigma * (NIMG * HW)
                             + ((size_t)(gc >> 10)) * HW + (size_t)gm * 1024 + (gc & 1023);
                    u16 h0, l0, h1, l1;
                    bf_split(v0, h0, l0);
                    bf_split(v1, h1, l1);
                    *(u32*)&g_Yh[o] = (u32)h0 | ((u32)h1 << 16);
                    *(u32*)&g_Yl[o] = (u32)l0 | ((u32)l1 << 16);
                } else {
                    // out: accS[sigma][gm = img*1024+y][gc = x]
                    size_t o = (size_t)sigma * (NIMG * HW) + (size_t)gm * 1024 + gc;
                    g_accS[o]     = logf(fmaxf(v0, EPSF));
                    g_accS[o + 1] = logf(fmaxf(v1, EPSF));
                }
            }
        }
    }
}

// ---------------------------------------------------------------------------
__global__ void fields_k(const float* __restrict__ inp, float* __restrict__ dout) {
    int total = NIMG * HW;
    for (int idx = blockIdx.x * blockDim.x + threadIdx.x; idx < total;
         idx += gridDim.x * blockDim.x) {
        float a = g_accS[idx] + g_accS[total + idx] + g_accS[2 * total + idx];
        float ib = a * (1.0f / 3.0f);
        float v  = inp[idx];
        float li = logf(fminf(fmaxf(v, EPSF), 1.0f));
        float refl  = li - ib;
        float illum = logf(fmaxf(v, EPSF)) - refl;
        dout[3 + idx]         = refl;
        dout[3 + total + idx] = illum;
    }
}

__global__ void grad_k(const float* __restrict__ dout) {
    const float* __restrict__ refl = dout + 3;
    const float* __restrict__ ill  = dout + 3 + NIMG * HW;
    float s0 = 0.f, s1 = 0.f, s2 = 0.f, s3 = 0.f;
    int total = NIMG * HW;
    for (int idx = blockIdx.x * blockDim.x + threadIdx.x; idx < total;
         idx += gridDim.x * blockDim.x) {
        int x = idx & 1023, y = (idx >> 10) & 1023;
        float r0 = refl[idx], i0 = ill[idx];
        if (x < 1023) { s0 += fabsf(r0 - refl[idx + 1]);    s2 += fabsf(i0 - ill[idx + 1]); }
        if (y < 1023) { s1 += fabsf(r0 - refl[idx + 1024]); s3 += fabsf(i0 - ill[idx + 1024]); }
    }
#pragma unroll
    for (int o = 16; o > 0; o >>= 1) {
        s0 += __shfl_down_sync(0xffffffffu, s0, o);
        s1 += __shfl_down_sync(0xffffffffu, s1, o);
        s2 += __shfl_down_sync(0xffffffffu, s2, o);
        s3 += __shfl_down_sync(0xffffffffu, s3, o);
    }
    __shared__ float sb[4][8];
    int wid = threadIdx.x >> 5, lid = threadIdx.x & 31;
    if (lid == 0) { sb[0][wid] = s0; sb[1][wid] = s1; sb[2][wid] = s2; sb[3][wid] = s3; }
    __syncthreads();
    if (threadIdx.x == 0) {
        float t0 = 0.f, t1 = 0.f, t2 = 0.f, t3 = 0.f;
        int nw = blockDim.x >> 5;
        for (int w = 0; w < nw; ++w) { t0 += sb[0][w]; t1 += sb[1][w]; t2 += sb[2][w]; t3 += sb[3][w]; }
        atomicAdd(&g_red[0], t0); atomicAdd(&g_red[1], t1);
        atomicAdd(&g_red[2], t2); atomicAdd(&g_red[3], t3);
    }
}

__global__ void fin_k(float* dout) {
    if (threadIdx.x == 0) {
        float ngx = (float)(NIMG * 1024 * 1023);
        float ngy = (float)(NIMG * 1023 * 1024);
        float ld = g_red[0] / ngx + g_red[1] / ngy;
        float ls = g_red[2] / ngx + g_red[3] / ngy;
        dout[0] = ls; dout[1] = ld; dout[2] = ls;   // DETAIL_W=0, ILLUM_W=1
    }
}

extern "C" void kernel_launch(void* const* d_in, const int* in_sizes, int n_in,
                              void* d_out, int out_size) {
    const float* inp = (const float*)d_in[0];
    float* out = (float*)d_out;

    cudaFuncSetAttribute(mma_k<1>, cudaFuncAttributeMaxDynamicSharedMemorySize, SMEM_MMA);
    cudaFuncSetAttribute(mma_k<2>, cudaFuncAttributeMaxDynamicSharedMemorySize, SMEM_MMA);

    init_kernels_k<<<1, 1024>>>();
    buildA_k<<<dim3(1024, 3), 256>>>();
    splitX_k<<<dim3(32, 32, NIMG), dim3(32, 32)>>>(inp);

    // sigma = blockIdx.x % 3 (interleaved load balance), all sigmas per launch
    mma_k<1><<<dim3(8 * 3, 48), MTHR, SMEM_MMA>>>();   // Y[s] = A_s * X      (tile 128x128)
    mma_k<2><<<dim3(48 * 3, 8), MTHR, SMEM_MMA>>>();   // accS[s] = log(Y_s * A_s^T)

    fields_k<<<4096, 256>>>(inp, out);
    grad_k<<<2048, 256>>>(out);
    fin_k<<<1, 32>>>(out);
}